// round 17
// baseline (speedup 1.0000x reference)
#include <cuda_runtime.h>
#include <cuda_fp16.h>
#include <cstdint>

#define B_TOT 1024
#define T_LEN 512
#define NU 64
#define NB 8
#define NCTA 128
#define THR 512

__device__ float g_h[(size_t)B_TOT * T_LEN * NU];

__device__ __forceinline__ float sigf(float x) {
    float t; asm("tanh.approx.f32 %0, %1;" : "=f"(t) : "f"(0.5f * x));
    return fmaf(0.5f, t, 0.5f);
}
__device__ __forceinline__ uint32_t pack_h2(__half a, __half b) {
    __half2 p; p.x = a; p.y = b; return *(uint32_t*)&p;
}
__device__ __forceinline__ void hmma(float* c, const uint32_t* a, uint32_t b0, uint32_t b1) {
    asm volatile("mma.sync.aligned.m16n8k16.row.col.f32.f16.f16.f32 "
        "{%0,%1,%2,%3}, {%4,%5,%6,%7}, {%8,%9}, {%0,%1,%2,%3};"
        : "+f"(c[0]), "+f"(c[1]), "+f"(c[2]), "+f"(c[3])
        : "r"(a[0]), "r"(a[1]), "r"(a[2]), "r"(a[3]), "r"(b0), "r"(b1));
}

// Warp-specialized: warps 0-7 = consumers (recurrence critical path only),
// warps 8-15 = producers (x-part staging + x-MMA, one step ahead).
// Consumer warp w owns units [8w,8w+8): tile0 m-rows = gates (i,f),
// tile1 = (g,o) => each lane holds all 4 gates of cells (u=8w+lr, b=2qq{,+1})
// directly in accumulator registers (no shuffles).
// Producer warp 8+w computes zx = x @ Wx-part with the SAME fragment mapping
// and hands it to consumer warp w via zxs smem slab (double buffered).
// fp16 2-term: z = Whi*Ahi + Whi*Alo. One __syncthreads per step.
template <int KX, bool LAST>
__global__ void __launch_bounds__(THR)
lstm_layer(const float* __restrict__ xin, const float* __restrict__ Wx,
           const float* __restrict__ U,   const float* __restrict__ bias)
{
    constexpr int KSX  = KX / 16;          // 4 or 0
    constexpr int KSXA = KSX ? KSX : 1;
    constexpr int PH   = 2 * NU + 8;       // 136 halves: hi[0,64) lo[64,128) pad

    __shared__ __half act[2][NB * PH];     // h tiles (hi/lo)
    __shared__ __half xbuf[2][NB * PH];    // x tiles (hi/lo), producer-private
    __shared__ float  zxs[2][8][32][8];    // zx handoff [buf][warp][lane][tau*4+c]
    __shared__ float  Xsh[2][NB];          // layer0 scalar x

    const int tid  = threadIdx.x;
    const int wid  = tid >> 5;
    const int lane = tid & 31;
    const int lr   = lane >> 2;
    const int qq   = lane & 3;
    const bool cons = (wid < 8);
    const int pw   = wid & 7;
    const int bg0  = blockIdx.x * NB;
    const int u    = 8 * pw + lr;
    const int bA   = 2 * qq;

    // ---- fragments ----
    uint32_t Wfh[4][2][4];                 // consumer: h-part (U rows)
    uint32_t Wfx[KSXA][2][4];              // producer: x-part (Wx rows)
    float bg[4], wxg[4];
    if (cons) {
        #pragma unroll
        for (int s2 = 0; s2 < 4; ++s2)
            #pragma unroll
            for (int tau = 0; tau < 2; ++tau)
                #pragma unroll
                for (int i = 0; i < 4; ++i) {
                    const int k = 16 * s2 + 2 * qq + ((i >> 1) << 3);
                    const int oc = u + 64 * (2 * tau + (i & 1));
                    Wfh[s2][tau][i] = pack_h2(
                        __float2half(U[(size_t)k * 256 + oc]),
                        __float2half(U[(size_t)(k + 1) * 256 + oc]));
                }
        #pragma unroll
        for (int g = 0; g < 4; ++g) {
            bg[g]  = bias[u + 64 * g];
            wxg[g] = (KX == 0) ? Wx[u + 64 * g] : 0.0f;
        }
    } else if (KX) {
        #pragma unroll
        for (int s = 0; s < KSXA; ++s)
            #pragma unroll
            for (int tau = 0; tau < 2; ++tau)
                #pragma unroll
                for (int i = 0; i < 4; ++i) {
                    const int k = 16 * s + 2 * qq + ((i >> 1) << 3);
                    const int oc = u + 64 * (2 * tau + (i & 1));
                    Wfx[s][tau][i] = pack_h2(
                        __float2half(Wx[(size_t)k * 256 + oc]),
                        __float2half(Wx[(size_t)(k + 1) * 256 + oc]));
                }
    }

    for (int i = tid; i < 2 * NB * PH; i += THR) (&act[0][0])[i] = __float2half(0.0f);

    // ---- pre-loop: stage x(0)->xbuf[1], x(1)->xbuf[0]; zx(0)->zxs[0] ----
    float xs = 0.0f;
    if (!cons) {
        if (KX) {
            #pragma unroll
            for (int j = 0; j < 2; ++j) {          // j=0: t=0->xbuf[1]; j=1: t=1->xbuf[0]
                const int tt = j;
                __half* xb = xbuf[1 - j];
                float v0 = g_h[((size_t)(bg0 + pw) * T_LEN + tt) * NU + lane];
                float v1 = g_h[((size_t)(bg0 + pw) * T_LEN + tt) * NU + lane + 32];
                __half h0 = __float2half(v0), h1 = __float2half(v1);
                xb[pw * PH + lane]           = h0;
                xb[pw * PH + 64 + lane]      = __float2half(v0 - __half2float(h0));
                xb[pw * PH + lane + 32]      = h1;
                xb[pw * PH + 64 + lane + 32] = __float2half(v1 - __half2float(h1));
            }
        } else if (wid == 8 && lane < NB) {
            Xsh[0][lane] = xin[(size_t)(bg0 + lane) * T_LEN + 0];
            xs = xin[(size_t)(bg0 + lane) * T_LEN + 1];
        }
    }
    __syncthreads();
    if (!cons && KX) {
        float zx[2][4] = {};
        #pragma unroll
        for (int s = 0; s < KSXA; ++s) {
            const uint32_t* bp = (const uint32_t*)(&xbuf[1][lr * PH + 16 * s + 2 * qq]);
            uint32_t b0 = bp[0], b1 = bp[4], b2 = bp[32], b3 = bp[36];
            hmma(zx[0], Wfx[s][0], b0, b1); hmma(zx[0], Wfx[s][0], b2, b3);
            hmma(zx[1], Wfx[s][1], b0, b1); hmma(zx[1], Wfx[s][1], b2, b3);
        }
        *(float4*)&zxs[0][pw][lane][0] = make_float4(zx[0][0], zx[0][1], zx[0][2], zx[0][3]);
        *(float4*)&zxs[0][pw][lane][4] = make_float4(zx[1][0], zx[1][1], zx[1][2], zx[1][3]);
    }
    __syncthreads();

    float cs[2] = {0.0f, 0.0f};

    for (int t = 0; t < T_LEN; ++t) {
        const int p = t & 1;
        if (cons) {
            const __half* ap = act[p];
            __half* an = act[p ^ 1];
            // (1) h-fragments
            uint32_t hf[4][4];
            #pragma unroll
            for (int s2 = 0; s2 < 4; ++s2) {
                const uint32_t* bp = (const uint32_t*)(ap + lr * PH + 16 * s2 + 2 * qq);
                hf[s2][0] = bp[0]; hf[s2][1] = bp[4];
                hf[s2][2] = bp[32]; hf[s2][3] = bp[36];
            }
            // (2) zx handoff (prefetch; hidden under HMMA)
            float zxv[8];
            if (KX) {
                float4 q0 = *(float4*)&zxs[p][pw][lane][0];
                float4 q1 = *(float4*)&zxs[p][pw][lane][4];
                zxv[0] = q0.x; zxv[1] = q0.y; zxv[2] = q0.z; zxv[3] = q0.w;
                zxv[4] = q1.x; zxv[5] = q1.y; zxv[6] = q1.z; zxv[7] = q1.w;
            }
            // (3) h-MMA: 16 HMMA, 4 independent chains
            float zh[2][2][4] = {};
            #pragma unroll
            for (int s2 = 0; s2 < 4; ++s2)
                #pragma unroll
                for (int tau = 0; tau < 2; ++tau) {
                    float* a = zh[tau][s2 & 1];
                    hmma(a, Wfh[s2][tau], hf[s2][0], hf[s2][1]);
                    hmma(a, Wfh[s2][tau], hf[s2][2], hf[s2][3]);
                }
            // (4) epilogue: 2 cells, gates lane-local
            #pragma unroll
            for (int cj = 0; cj < 2; ++cj) {
                float zi = zh[0][0][cj]     + zh[0][1][cj]     + bg[0];
                float zf = zh[0][0][cj + 2] + zh[0][1][cj + 2] + bg[1];
                float zg = zh[1][0][cj]     + zh[1][1][cj]     + bg[2];
                float zo = zh[1][0][cj + 2] + zh[1][1][cj + 2] + bg[3];
                if (KX) {
                    zi += zxv[cj];     zf += zxv[cj + 2];
                    zg += zxv[4 + cj]; zo += zxv[6 + cj];
                } else {
                    float xr = Xsh[p][bA + cj];
                    zi = fmaf(xr, wxg[0], zi); zf = fmaf(xr, wxg[1], zf);
                    zg = fmaf(xr, wxg[2], zg); zo = fmaf(xr, wxg[3], zo);
                }
                float cn = fmaf(sigf(zf), cs[cj], sigf(zi) * fmaxf(zg, 0.0f));
                cs[cj] = cn;
                float h = sigf(zo) * fmaxf(cn, 0.0f);
                const int b = bA + cj;
                __half hh = __float2half(h);
                an[b * PH + u]      = hh;
                an[b * PH + 64 + u] = __float2half(h - __half2float(hh));
                if (!LAST || t == T_LEN - 1)
                    g_h[((size_t)(bg0 + b) * T_LEN + t) * NU + u] = h;
            }
        } else if (KX) {
            // producer: zx(t+1) from xbuf[p]; stage x(t+2) into xbuf[p^1]
            float zx[2][4] = {};
            #pragma unroll
            for (int s = 0; s < KSXA; ++s) {
                const uint32_t* bp = (const uint32_t*)(&xbuf[p][lr * PH + 16 * s + 2 * qq]);
                uint32_t b0 = bp[0], b1 = bp[4], b2 = bp[32], b3 = bp[36];
                hmma(zx[0], Wfx[s][0], b0, b1); hmma(zx[0], Wfx[s][0], b2, b3);
                hmma(zx[1], Wfx[s][1], b0, b1); hmma(zx[1], Wfx[s][1], b2, b3);
            }
            *(float4*)&zxs[p ^ 1][pw][lane][0] = make_float4(zx[0][0], zx[0][1], zx[0][2], zx[0][3]);
            *(float4*)&zxs[p ^ 1][pw][lane][4] = make_float4(zx[1][0], zx[1][1], zx[1][2], zx[1][3]);
            const int tn2 = (t + 2 < T_LEN) ? t + 2 : T_LEN - 1;
            float v0 = g_h[((size_t)(bg0 + pw) * T_LEN + tn2) * NU + lane];
            float v1 = g_h[((size_t)(bg0 + pw) * T_LEN + tn2) * NU + lane + 32];
            __half* xb = xbuf[p ^ 1];
            __half h0 = __float2half(v0), h1 = __float2half(v1);
            xb[pw * PH + lane]           = h0;
            xb[pw * PH + 64 + lane]      = __float2half(v0 - __half2float(h0));
            xb[pw * PH + lane + 32]      = h1;
            xb[pw * PH + 64 + lane + 32] = __float2half(v1 - __half2float(h1));
        } else {
            if (wid == 8 && lane < NB) {
                Xsh[p ^ 1][lane] = xs;
                const int tn2 = (t + 2 < T_LEN) ? t + 2 : T_LEN - 1;
                xs = xin[(size_t)(bg0 + lane) * T_LEN + tn2];
            }
        }
        __syncthreads();   // publishes act[p^1] h-part, xbuf[p^1], zxs[p^1]
    }
}

__global__ void __launch_bounds__(256)
head_kernel(const float* __restrict__ Wd, const float* __restrict__ bd,
            float* __restrict__ out)
{
    __shared__ float wd[NU];
    if (threadIdx.x < NU) wd[threadIdx.x] = Wd[threadIdx.x];
    __syncthreads();
    int b = blockIdx.x * blockDim.x + threadIdx.x;
    const float* hp = g_h + ((size_t)b * T_LEN + (T_LEN - 1)) * NU;
    float s = 0.0f;
    #pragma unroll
    for (int u = 0; u < NU; ++u) s += hp[u] * wd[u];
    out[b] = s + bd[0];
}

extern "C" void kernel_launch(void* const* d_in, const int* in_sizes, int n_in,
                              void* d_out, int out_size)
{
    const float* x   = (const float*)d_in[0];
    const float* Wx0 = (const float*)d_in[1];
    const float* U0  = (const float*)d_in[2];
    const float* b0  = (const float*)d_in[3];
    const float* Wx1 = (const float*)d_in[4];
    const float* U1  = (const float*)d_in[5];
    const float* b1  = (const float*)d_in[6];
    const float* Wx2 = (const float*)d_in[7];
    const float* U2  = (const float*)d_in[8];
    const float* b2  = (const float*)d_in[9];
    const float* Wx3 = (const float*)d_in[10];
    const float* U3  = (const float*)d_in[11];
    const float* b3  = (const float*)d_in[12];
    const float* Wd  = (const float*)d_in[13];
    const float* bd  = (const float*)d_in[14];
    float* out = (float*)d_out;

    lstm_layer<0,  false><<<NCTA, THR>>>(x,       Wx0, U0, b0);
    lstm_layer<64, false><<<NCTA, THR>>>(nullptr, Wx1, U1, b1);
    lstm_layer<64, false><<<NCTA, THR>>>(nullptr, Wx2, U2, b2);
    lstm_layer<64, true ><<<NCTA, THR>>>(nullptr, Wx3, U3, b3);
    head_kernel<<<B_TOT / 256, 256>>>(Wd, bd, out);
}